// round 13
// baseline (speedup 1.0000x reference)
#include <cuda_runtime.h>
#include <cuda_fp16.h>
#include <math.h>

#define Bb 4
#define Cc 64
#define Hh 256
#define Ww 256
#define PP (Hh*Ww)          // 65536
#define CH 32

// ---------------- scratch: channel-pair interleaved fp16 -----------------------
__device__ __half2 g_t02[Bb*32*PP];
__device__ __half2 g_dir2[4][Bb*32*PP];   // 0=up 1=right 2=down 3=left
__device__ __half2 g_t22[Bb*32*PP];
__device__ __half2 g_a12[Bb*16*PP];
__device__ __half2 g_a22[Bb*16*PP];
// half2 k-pair-packed weights
__device__ __half2 g_win2[32*64];         // [k2*64+oc]
__device__ __half2 g_wD22[4*32*64];       // [d][k2*64+oc]
__device__ __half2 g_w3h0[32*9*32];       // [(ic2*9+tap)*32+oc]
__device__ __half2 g_w3h1[16*9*32];

// ---------------- fp16 mma m16n8k16, fp32 accumulate ---------------------------
__device__ __forceinline__ void mma_f16(float* c, const unsigned* a, const unsigned* b) {
    asm volatile("mma.sync.aligned.m16n8k16.row.col.f32.f16.f16.f32 "
        "{%0,%1,%2,%3}, {%4,%5,%6,%7}, {%8,%9}, {%0,%1,%2,%3};"
        : "+f"(c[0]), "+f"(c[1]), "+f"(c[2]), "+f"(c[3])
        : "r"(a[0]), "r"(a[1]), "r"(a[2]), "r"(a[3]), "r"(b[0]), "r"(b[1]));
}
__device__ __forceinline__ unsigned h2u(__half2 h) { return *reinterpret_cast<unsigned*>(&h); }
__device__ __forceinline__ unsigned packh2(float a, float b) {
    __half2 t = __floats2half2_rn(a, b);
    return *reinterpret_cast<unsigned*>(&t);
}

// Pair-interleave epilogue (see R10): merge D rows (lr, lr+8) into channel pairs.
__device__ __forceinline__ uint2 pair_merge(unsigned u01, unsigned u23, bool even) {
    unsigned r01 = __shfl_xor_sync(0xffffffffu, u01, 4);
    unsigned r23 = __shfl_xor_sync(0xffffffffu, u23, 4);
    unsigned a = even ? u01 : r23;
    unsigned b = even ? r01 : u23;
    return make_uint2(__byte_perm(a, b, 0x5410), __byte_perm(a, b, 0x7632));
}

// ================================================================================
// K0: weight transpose + half2 k-pair packing.
// ================================================================================
__global__ __launch_bounds__(256)
void k_prep(const float* __restrict__ w_in, const float* __restrict__ wD2,
            const float* __restrict__ a1w, const float* __restrict__ a2w) {
    int idx = blockIdx.x * 256 + threadIdx.x;
    if (idx < 2048) {
        int k2 = idx >> 6, oc = idx & 63;
        g_win2[idx] = __floats2half2_rn(w_in[oc*64 + 2*k2], w_in[oc*64 + 2*k2 + 1]);
        return;
    }
    idx -= 2048;
    if (idx < 4*2048) {
        int d = idx >> 11, r = idx & 2047;
        int k2 = r >> 6, oc = r & 63;
        g_wD22[idx] = __floats2half2_rn(wD2[oc*256 + d*64 + 2*k2],
                                        wD2[oc*256 + d*64 + 2*k2 + 1]);
        return;
    }
    idx -= 4*2048;
    if (idx < 32*9*32) {
        int oc = idx & 31, tap = (idx >> 5) % 9, ic2 = idx / (9*32);
        g_w3h0[idx] = __floats2half2_rn(a1w[(oc*64 + 2*ic2)*9 + tap],
                                        a1w[(oc*64 + 2*ic2 + 1)*9 + tap]);
        return;
    }
    idx -= 32*9*32;
    if (idx < 16*9*32) {
        int oc = idx & 31, tap = (idx >> 5) % 9, ic2 = idx / (9*32);
        g_w3h1[idx] = __floats2half2_rn(a2w[(oc*32 + 2*ic2)*9 + tap],
                                        a2w[(oc*32 + 2*ic2 + 1)*9 + tap]);
    }
}

// ================================================================================
// K1: t0 = w_in @ x. 128 thr/4 warps, tile 64oc x 128px, K=64. Interleaved output.
// ================================================================================
__global__ __launch_bounds__(128)
void k_conv_in(const float* __restrict__ x) {
    __shared__ __align__(16) __half2 ws2s[32][72];
    __shared__ __align__(16) __half2 xs2s[32][136];
    int tid  = threadIdx.x;
    int lane = tid & 31, warp = tid >> 5;
    int lr = lane >> 2, lc = lane & 3;
    int blk = blockIdx.x;                 // 2048
    int b   = blk >> 9;
    int p0g = (blk & 511) * 128;
    int oc0 = warp * 16;

    for (int t = tid; t < 2048; t += 128) {
        int k2 = t >> 6, oc = t & 63;
        ws2s[k2][oc] = g_win2[t];
    }
    const float* src = x + (size_t)b*64*PP + p0g;
    for (int t = tid; t < 1024; t += 128) {
        int k2 = t >> 5, px4 = (t & 31) * 4;
        float4 v0 = *(const float4*)&src[(size_t)(2*k2)*PP + px4];
        float4 v1 = *(const float4*)&src[(size_t)(2*k2+1)*PP + px4];
        __half2 tmp[4];
        tmp[0] = __floats2half2_rn(v0.x, v1.x);
        tmp[1] = __floats2half2_rn(v0.y, v1.y);
        tmp[2] = __floats2half2_rn(v0.z, v1.z);
        tmp[3] = __floats2half2_rn(v0.w, v1.w);
        *(uint4*)&xs2s[k2][px4] = *(uint4*)tmp;
    }
    __syncthreads();

    float acc[16][4];
    #pragma unroll
    for (int j = 0; j < 16; j++) { acc[j][0]=0.f; acc[j][1]=0.f; acc[j][2]=0.f; acc[j][3]=0.f; }

    #pragma unroll
    for (int kk = 0; kk < 4; kk++) {
        unsigned a[4];
        a[0] = h2u(ws2s[8*kk+lc]  [oc0+lr]);
        a[1] = h2u(ws2s[8*kk+lc]  [oc0+lr+8]);
        a[2] = h2u(ws2s[8*kk+lc+4][oc0+lr]);
        a[3] = h2u(ws2s[8*kk+lc+4][oc0+lr+8]);
        #pragma unroll
        for (int j = 0; j < 16; j++) {
            unsigned bfr[2];
            bfr[0] = h2u(xs2s[8*kk+lc]  [8*j+lr]);
            bfr[1] = h2u(xs2s[8*kk+lc+4][8*j+lr]);
            mma_f16(acc[j], a, bfr);
        }
    }
    __half2* dst2 = g_t02 + (size_t)b*32*PP + p0g;
    bool even = (lr & 1) == 0;
    int m = even ? (lr >> 1) : ((lr - 1) >> 1);
    int oc2 = 8*warp + (even ? m : 4 + m);
    #pragma unroll
    for (int j = 0; j < 16; j++) {
        unsigned u01 = packh2(acc[j][0], acc[j][1]);
        unsigned u23 = packh2(acc[j][2], acc[j][3]);
        uint2 v = pair_merge(u01, u23, even);
        *(uint2*)&dst2[(size_t)oc2*PP + 8*j + 2*lc] = v;
    }
}

// ================================================================================
// K2v: vertical scans, BOTH directions per thread (4 indep fp32 chains).
// grid (128, 2): plane, w-half. Opposing walks re-hit L2.
// ================================================================================
__global__ __launch_bounds__(128)
void k_scan_v(const float* __restrict__ w_up, const float* __restrict__ b_up,
              const float* __restrict__ w_down, const float* __restrict__ b_down) {
    int plane = blockIdx.x;               // b*32 + k2
    int w     = blockIdx.y * 128 + threadIdx.x;
    int k2    = plane & 31;
    const __half2* src = g_t02 + (size_t)plane*PP;
    __half2* dd = g_dir2[2] + (size_t)plane*PP;   // down
    __half2* du = g_dir2[0] + (size_t)plane*PP;   // up
    float wd0 = w_down[2*k2], wd1 = w_down[2*k2+1];
    float bd0 = b_down[2*k2], bd1 = b_down[2*k2+1];
    float wu0 = w_up[2*k2],   wu1 = w_up[2*k2+1];
    float bu0 = b_up[2*k2],   bu1 = b_up[2*k2+1];
    float hd0 = 0.f, hd1 = 0.f, hu0 = 0.f, hu1 = 0.f;
    #pragma unroll 4
    for (int y = 0; y < Hh; y++) {
        float2 vd = __half22float2(src[y*Ww + w]);
        float2 vu = __half22float2(src[(Hh-1-y)*Ww + w]);
        hd0 = fmaxf(fmaf(wd0, hd0, vd.x + bd0), 0.f);
        hd1 = fmaxf(fmaf(wd1, hd1, vd.y + bd1), 0.f);
        hu0 = fmaxf(fmaf(wu0, hu0, vu.x + bu0), 0.f);
        hu1 = fmaxf(fmaf(wu1, hu1, vu.y + bu1), 0.f);
        dd[y*Ww + w]        = __floats2half2_rn(hd0, hd1);
        du[(Hh-1-y)*Ww + w] = __floats2half2_rn(hu0, hu1);
    }
}

// ================================================================================
// K2h: horizontal scans, BOTH directions per warp (4 indep chains/thread).
// grid (128, 2): plane, row-half. Two tile buffers (right chunk ch, left 7-ch).
// ================================================================================
__global__ __launch_bounds__(128)
void k_scan_h(const float* __restrict__ w_right, const float* __restrict__ b_right,
              const float* __restrict__ w_left, const float* __restrict__ b_left) {
    __shared__ __half2 sR[4][32][33];
    __shared__ __half2 sL[4][32][33];
    int plane = blockIdx.x;
    int k2    = plane & 31;
    int lane = threadIdx.x & 31, warp = threadIdx.x >> 5;
    const __half2* src = g_t02 + (size_t)plane*PP;
    __half2* dr = g_dir2[1] + (size_t)plane*PP;   // right
    __half2* dl = g_dir2[3] + (size_t)plane*PP;   // left
    float wr0 = w_right[2*k2], wr1 = w_right[2*k2+1];
    float br0 = b_right[2*k2], br1 = b_right[2*k2+1];
    float wl0 = w_left[2*k2],  wl1 = w_left[2*k2+1];
    float bl0 = b_left[2*k2],  bl1 = b_left[2*k2+1];
    int row0 = blockIdx.y * 128 + warp * 32;
    float hr0 = 0.f, hr1 = 0.f, hl0 = 0.f, hl1 = 0.f;
    for (int ch = 0; ch < 8; ch++) {
        int c0r = ch*32;
        int c0l = 224 - ch*32;
        #pragma unroll
        for (int r = 0; r < 32; r++) {
            sR[warp][r][lane] = src[(row0 + r)*Ww + c0r + lane];
            sL[warp][r][lane] = src[(row0 + r)*Ww + c0l + lane];
        }
        __syncwarp();
        #pragma unroll
        for (int j = 0; j < 32; j++) {
            float2 vr = __half22float2(sR[warp][lane][j]);
            hr0 = fmaxf(fmaf(wr0, hr0, vr.x + br0), 0.f);
            hr1 = fmaxf(fmaf(wr1, hr1, vr.y + br1), 0.f);
            sR[warp][lane][j] = __floats2half2_rn(hr0, hr1);
            int jl = 31 - j;
            float2 vl = __half22float2(sL[warp][lane][jl]);
            hl0 = fmaxf(fmaf(wl0, hl0, vl.x + bl0), 0.f);
            hl1 = fmaxf(fmaf(wl1, hl1, vl.y + bl1), 0.f);
            sL[warp][lane][jl] = __floats2half2_rn(hl0, hl1);
        }
        __syncwarp();
        #pragma unroll
        for (int r = 0; r < 32; r++) {
            dr[(row0 + r)*Ww + c0r + lane] = sR[warp][r][lane];
            dl[(row0 + r)*Ww + c0l + lane] = sL[warp][r][lane];
        }
        __syncwarp();
    }
}

// ================================================================================
// K3: t2 = relu(wD2 @ cat). Register-pipelined d-chunk staging: LDGs for chunk
// d+1 issue before the MMAs of chunk d, commit to smem after compute sync.
// ================================================================================
__global__ __launch_bounds__(128)
void k_convD2() {
    __shared__ __align__(16) __half2 ws2s[32][72];
    __shared__ __align__(16) __half2 xs2s[32][136];
    int tid  = threadIdx.x;
    int lane = tid & 31, warp = tid >> 5;
    int lr = lane >> 2, lc = lane & 3;
    int blk = blockIdx.x;                 // 2048
    int b   = blk >> 9;
    int p0g = (blk & 511) * 128;
    int oc0 = warp * 16;
    size_t base = (size_t)b*32*PP + p0g;

    float acc[16][4];
    #pragma unroll
    for (int j = 0; j < 16; j++) { acc[j][0]=0.f; acc[j][1]=0.f; acc[j][2]=0.f; acc[j][3]=0.f; }

    unsigned wr[16];
    uint4 xr[8];

    // load chunk 0 into regs, commit
    {
        const __half2* wsrc = g_wD22;
        #pragma unroll
        for (int i = 0; i < 16; i++) wr[i] = h2u(wsrc[tid + 128*i]);
        const __half2* srcd = g_dir2[0] + base;
        #pragma unroll
        for (int i = 0; i < 8; i++) {
            int t = tid + 128*i;
            int k2 = t >> 5, px4 = (t & 31) * 4;
            xr[i] = *(const uint4*)&srcd[(size_t)k2*PP + px4];
        }
    }
    #pragma unroll
    for (int i = 0; i < 16; i++) {
        int t = tid + 128*i;
        __half2 h; *reinterpret_cast<unsigned*>(&h) = wr[i];
        ws2s[t >> 6][t & 63] = h;
    }
    #pragma unroll
    for (int i = 0; i < 8; i++) {
        int t = tid + 128*i;
        int k2 = t >> 5, px4 = (t & 31) * 4;
        *(uint4*)&xs2s[k2][px4] = xr[i];
    }
    __syncthreads();

    for (int d = 0; d < 4; d++) {
        if (d < 3) {                         // prefetch next chunk into regs
            const __half2* wsrc = g_wD22 + (d+1)*2048;
            #pragma unroll
            for (int i = 0; i < 16; i++) wr[i] = h2u(wsrc[tid + 128*i]);
            const __half2* srcd = g_dir2[d+1] + base;
            #pragma unroll
            for (int i = 0; i < 8; i++) {
                int t = tid + 128*i;
                int k2 = t >> 5, px4 = (t & 31) * 4;
                xr[i] = *(const uint4*)&srcd[(size_t)k2*PP + px4];
            }
        }
        #pragma unroll
        for (int kk = 0; kk < 4; kk++) {
            unsigned a[4];
            a[0] = h2u(ws2s[8*kk+lc]  [oc0+lr]);
            a[1] = h2u(ws2s[8*kk+lc]  [oc0+lr+8]);
            a[2] = h2u(ws2s[8*kk+lc+4][oc0+lr]);
            a[3] = h2u(ws2s[8*kk+lc+4][oc0+lr+8]);
            #pragma unroll
            for (int j = 0; j < 16; j++) {
                unsigned bfr[2];
                bfr[0] = h2u(xs2s[8*kk+lc]  [8*j+lr]);
                bfr[1] = h2u(xs2s[8*kk+lc+4][8*j+lr]);
                mma_f16(acc[j], a, bfr);
            }
        }
        if (d < 3) {
            __syncthreads();
            #pragma unroll
            for (int i = 0; i < 16; i++) {
                int t = tid + 128*i;
                __half2 h; *reinterpret_cast<unsigned*>(&h) = wr[i];
                ws2s[t >> 6][t & 63] = h;
            }
            #pragma unroll
            for (int i = 0; i < 8; i++) {
                int t = tid + 128*i;
                int k2 = t >> 5, px4 = (t & 31) * 4;
                *(uint4*)&xs2s[k2][px4] = xr[i];
            }
            __syncthreads();
        }
    }
    __half2* dst2 = g_t22 + base;
    bool even = (lr & 1) == 0;
    int m = even ? (lr >> 1) : ((lr - 1) >> 1);
    int oc2 = 8*warp + (even ? m : 4 + m);
    #pragma unroll
    for (int j = 0; j < 16; j++) {
        unsigned u01 = packh2(fmaxf(acc[j][0],0.f), fmaxf(acc[j][1],0.f));
        unsigned u23 = packh2(fmaxf(acc[j][2],0.f), fmaxf(acc[j][3],0.f));
        uint2 v = pair_merge(u01, u23, even);
        *(uint2*)&dst2[(size_t)oc2*PP + 8*j + 2*lc] = v;
    }
}

// ================================================================================
// K4/K5: conv3x3 SAME + relu via fp16 mma. Interleaved src: single half2 loads.
// ================================================================================
template<int IC, int LAYER>
__global__ __launch_bounds__(128)
void k_conv3(const float* __restrict__ bias) {
    __shared__ __align__(16) __half2 wsm2[9][8][40];
    __shared__ __align__(16) __half2 in_s2[8][10][36];

    const __half2* src2 = (LAYER == 0) ? g_t22 : g_a12;
    __half2*       dst2 = (LAYER == 0) ? g_a12 : g_a22;
    const __half2* wT   = (LAYER == 0) ? g_w3h0 : g_w3h1;
    constexpr int ICP = IC/2;

    int tid  = threadIdx.x;
    int lane = tid & 31, warp = tid >> 5;
    int lr = lane >> 2, lc = lane & 3;
    int blk = blockIdx.x;                              // 1024
    int b   = blk >> 8;
    int t   = blk & 255;
    int ty0 = (t >> 3) * 8;
    int tx0 = (t & 7) * 32;
    const __half2* sb = src2 + (size_t)b*ICP*PP;

    float acc[2][8][4];
    #pragma unroll
    for (int m = 0; m < 2; m++)
        #pragma unroll
        for (int j = 0; j < 8; j++)
            { acc[m][j][0]=0.f; acc[m][j][1]=0.f; acc[m][j][2]=0.f; acc[m][j][3]=0.f; }

    for (int ic20 = 0; ic20 < ICP; ic20 += 8) {
        __syncthreads();
        for (int tt = tid; tt < 8*9*32; tt += 128) {
            int oc = tt & 31;
            int q  = tt >> 5;
            int tap = q % 9, icl2 = q / 9;
            wsm2[tap][icl2][oc] = wT[((ic20 + icl2)*9 + tap)*32 + oc];
        }
        for (int tt = tid; tt < 8*10*34; tt += 128) {
            int col = tt % 34;
            int rr  = (tt / 34) % 10;
            int icl2 = tt / 340;
            int gy = ty0 + rr - 1, gx = tx0 + col - 1;
            __half2 v = __floats2half2_rn(0.f, 0.f);
            if (gy >= 0 && gy < Hh && gx >= 0 && gx < Ww)
                v = sb[(size_t)(ic20 + icl2)*PP + gy*Ww + gx];
            in_s2[icl2][rr][col] = v;
        }
        __syncthreads();

        #pragma unroll
        for (int tap = 0; tap < 9; tap++) {
            int dy = tap / 3, dx = tap % 3;
            unsigned aA[4], aB[4];
            aA[0] = h2u(wsm2[tap][lc]  [lr]);
            aA[1] = h2u(wsm2[tap][lc]  [lr+8]);
            aA[2] = h2u(wsm2[tap][lc+4][lr]);
            aA[3] = h2u(wsm2[tap][lc+4][lr+8]);
            aB[0] = h2u(wsm2[tap][lc]  [lr+16]);
            aB[1] = h2u(wsm2[tap][lc]  [lr+24]);
            aB[2] = h2u(wsm2[tap][lc+4][lr+16]);
            aB[3] = h2u(wsm2[tap][lc+4][lr+24]);
            #pragma unroll
            for (int j = 0; j < 8; j++) {
                int y = 2*warp + (j >> 2);
                int x = 8*(j & 3) + lr;
                unsigned bfr[2];
                bfr[0] = h2u(in_s2[lc]  [y+dy][x+dx]);
                bfr[1] = h2u(in_s2[lc+4][y+dy][x+dx]);
                mma_f16(acc[0][j], aA, bfr);
                mma_f16(acc[1][j], aB, bfr);
            }
        }
    }
    bool even = (lr & 1) == 0;
    int q = even ? (lr >> 1) : ((lr - 1) >> 1);
    #pragma unroll
    for (int m = 0; m < 2; m++) {
        int ocA = 16*m + lr, ocB = 16*m + lr + 8;
        float bA = bias[ocA], bB = bias[ocB];
        int oc2 = 8*m + (even ? q : 4 + q);
        #pragma unroll
        for (int j = 0; j < 8; j++) {
            int py = ty0 + 2*warp + (j >> 2);
            int px = tx0 + 8*(j & 3) + 2*lc;
            unsigned u01 = packh2(fmaxf(acc[m][j][0]+bA,0.f), fmaxf(acc[m][j][1]+bA,0.f));
            unsigned u23 = packh2(fmaxf(acc[m][j][2]+bB,0.f), fmaxf(acc[m][j][3]+bB,0.f));
            uint2 v = pair_merge(u01, u23, even);
            *(uint2*)&dst2[((size_t)b*16 + oc2)*PP + py*Ww + px] = v;
        }
    }
}

// ================================================================================
// K6: a = a3w @ a2 + a3b ; weight = sigmoid(a) ; out = relu(x * weight)
// ================================================================================
__global__ __launch_bounds__(256)
void k_final(const float* __restrict__ x, const float* __restrict__ a3w,
             const float* __restrict__ a3b, float* __restrict__ out) {
    int idx = blockIdx.x * 256 + threadIdx.x;       // 65536 groups of 4 px
    int b  = idx >> 14;
    int p4 = (idx & 16383) * 4;
    const __half2* a2 = g_a22 + (size_t)b*16*PP;
    float4 acc = make_float4(0.f, 0.f, 0.f, 0.f);
    #pragma unroll
    for (int ic2 = 0; ic2 < 16; ic2++) {
        float w0 = a3w[2*ic2], w1 = a3w[2*ic2+1];
        uint4 raw = *(const uint4*)&a2[(size_t)ic2*PP + p4];
        __half2* h = (__half2*)&raw;
        float2 f0 = __half22float2(h[0]);
        float2 f1 = __half22float2(h[1]);
        float2 f2 = __half22float2(h[2]);
        float2 f3 = __half22float2(h[3]);
        acc.x += w0*f0.x + w1*f0.y;
        acc.y += w0*f1.x + w1*f1.y;
        acc.z += w0*f2.x + w1*f2.y;
        acc.w += w0*f3.x + w1*f3.y;
    }
    float bb = a3b[0];
    float4 wt;
    wt.x = 1.f / (1.f + expf(-(acc.x + bb)));
    wt.y = 1.f / (1.f + expf(-(acc.y + bb)));
    wt.z = 1.f / (1.f + expf(-(acc.z + bb)));
    wt.w = 1.f / (1.f + expf(-(acc.w + bb)));
    #pragma unroll 4
    for (int c = 0; c < 64; c++) {
        float4 xv = *(const float4*)&x[((size_t)b*64 + c)*PP + p4];
        float4 o;
        o.x = fmaxf(xv.x * wt.x, 0.f);
        o.y = fmaxf(xv.y * wt.y, 0.f);
        o.z = fmaxf(xv.z * wt.z, 0.f);
        o.w = fmaxf(xv.w * wt.w, 0.f);
        *(float4*)&out[((size_t)b*64 + c)*PP + p4] = o;
    }
}

// ================================================================================
extern "C" void kernel_launch(void* const* d_in, const int* in_sizes, int n_in,
                              void* d_out, int out_size) {
    const float* x       = (const float*)d_in[0];
    const float* w_in    = (const float*)d_in[1];
    const float* w_up    = (const float*)d_in[2];
    const float* b_up    = (const float*)d_in[3];
    const float* w_right = (const float*)d_in[4];
    const float* b_right = (const float*)d_in[5];
    const float* w_down  = (const float*)d_in[6];
    const float* b_down  = (const float*)d_in[7];
    const float* w_left  = (const float*)d_in[8];
    const float* b_left  = (const float*)d_in[9];
    const float* wD2     = (const float*)d_in[10];
    const float* a1w     = (const float*)d_in[11];
    const float* a1b     = (const float*)d_in[12];
    const float* a2w     = (const float*)d_in[13];
    const float* a2b     = (const float*)d_in[14];
    const float* a3w     = (const float*)d_in[15];
    const float* a3b     = (const float*)d_in[16];
    float* out = (float*)d_out;

    k_prep<<<94, 256>>>(w_in, wD2, a1w, a2w);
    k_conv_in<<<2048, 128>>>(x);
    dim3 gscan(Bb*32, 2);
    k_scan_v<<<gscan, 128>>>(w_up, b_up, w_down, b_down);
    k_scan_h<<<gscan, 128>>>(w_right, b_right, w_left, b_left);
    k_convD2<<<2048, 128>>>();
    k_conv3<64, 0><<<1024, 128>>>(a1b);
    k_conv3<32, 1><<<1024, 128>>>(a2b);
    k_final<<<256, 256>>>(x, a3w, a3b, out);
}

// round 16
// speedup vs baseline: 1.2644x; 1.2644x over previous
#include <cuda_runtime.h>
#include <cuda_fp16.h>
#include <math.h>

#define Bb 4
#define Cc 64
#define Hh 256
#define Ww 256
#define PP (Hh*Ww)          // 65536
#define CH 32

// ---------------- scratch: channel-pair interleaved fp16 -----------------------
__device__ __half2 g_t02[Bb*32*PP];
__device__ __half2 g_dir2[4][Bb*32*PP];   // 0=up 1=right 2=down 3=left
__device__ __half2 g_t22[Bb*32*PP];
__device__ __half2 g_a12[Bb*16*PP];
__device__ __half2 g_a22[Bb*16*PP];
// half2 k-pair-packed weights
__device__ __half2 g_win2[32*64];         // [k2*64+oc]
__device__ __half2 g_wD22[4*32*64];       // [d][k2*64+oc]
__device__ __half2 g_w3h0[32*9*32];       // [(ic2*9+tap)*32+oc]
__device__ __half2 g_w3h1[16*9*32];

// ---------------- fp16 mma m16n8k16, fp32 accumulate ---------------------------
__device__ __forceinline__ void mma_f16(float* c, const unsigned* a, const unsigned* b) {
    asm volatile("mma.sync.aligned.m16n8k16.row.col.f32.f16.f16.f32 "
        "{%0,%1,%2,%3}, {%4,%5,%6,%7}, {%8,%9}, {%0,%1,%2,%3};"
        : "+f"(c[0]), "+f"(c[1]), "+f"(c[2]), "+f"(c[3])
        : "r"(a[0]), "r"(a[1]), "r"(a[2]), "r"(a[3]), "r"(b[0]), "r"(b[1]));
}
__device__ __forceinline__ unsigned h2u(__half2 h) { return *reinterpret_cast<unsigned*>(&h); }
__device__ __forceinline__ unsigned packh2(float a, float b) {
    __half2 t = __floats2half2_rn(a, b);
    return *reinterpret_cast<unsigned*>(&t);
}

// Pair-interleave epilogue: merge D rows (lr, lr+8) into channel pairs.
__device__ __forceinline__ uint2 pair_merge(unsigned u01, unsigned u23, bool even) {
    unsigned r01 = __shfl_xor_sync(0xffffffffu, u01, 4);
    unsigned r23 = __shfl_xor_sync(0xffffffffu, u23, 4);
    unsigned a = even ? u01 : r23;
    unsigned b = even ? r01 : u23;
    return make_uint2(__byte_perm(a, b, 0x5410), __byte_perm(a, b, 0x7632));
}

// ================================================================================
// K0: weight transpose + half2 k-pair packing.
// ================================================================================
__global__ __launch_bounds__(256)
void k_prep(const float* __restrict__ w_in, const float* __restrict__ wD2,
            const float* __restrict__ a1w, const float* __restrict__ a2w) {
    int idx = blockIdx.x * 256 + threadIdx.x;
    if (idx < 2048) {
        int k2 = idx >> 6, oc = idx & 63;
        g_win2[idx] = __floats2half2_rn(w_in[oc*64 + 2*k2], w_in[oc*64 + 2*k2 + 1]);
        return;
    }
    idx -= 2048;
    if (idx < 4*2048) {
        int d = idx >> 11, r = idx & 2047;
        int k2 = r >> 6, oc = r & 63;
        g_wD22[idx] = __floats2half2_rn(wD2[oc*256 + d*64 + 2*k2],
                                        wD2[oc*256 + d*64 + 2*k2 + 1]);
        return;
    }
    idx -= 4*2048;
    if (idx < 32*9*32) {
        int oc = idx & 31, tap = (idx >> 5) % 9, ic2 = idx / (9*32);
        g_w3h0[idx] = __floats2half2_rn(a1w[(oc*64 + 2*ic2)*9 + tap],
                                        a1w[(oc*64 + 2*ic2 + 1)*9 + tap]);
        return;
    }
    idx -= 32*9*32;
    if (idx < 16*9*32) {
        int oc = idx & 31, tap = (idx >> 5) % 9, ic2 = idx / (9*32);
        g_w3h1[idx] = __floats2half2_rn(a2w[(oc*32 + 2*ic2)*9 + tap],
                                        a2w[(oc*32 + 2*ic2 + 1)*9 + tap]);
    }
}

// ================================================================================
// K1: t0 = w_in @ x. 128 thr/4 warps, tile 64oc x 128px, K=64. Interleaved output.
// ================================================================================
__global__ __launch_bounds__(128)
void k_conv_in(const float* __restrict__ x) {
    __shared__ __align__(16) __half2 ws2s[32][72];
    __shared__ __align__(16) __half2 xs2s[32][136];
    int tid  = threadIdx.x;
    int lane = tid & 31, warp = tid >> 5;
    int lr = lane >> 2, lc = lane & 3;
    int blk = blockIdx.x;                 // 2048
    int b   = blk >> 9;
    int p0g = (blk & 511) * 128;
    int oc0 = warp * 16;

    for (int t = tid; t < 2048; t += 128) {
        int k2 = t >> 6, oc = t & 63;
        ws2s[k2][oc] = g_win2[t];
    }
    const float* src = x + (size_t)b*64*PP + p0g;
    for (int t = tid; t < 1024; t += 128) {
        int k2 = t >> 5, px4 = (t & 31) * 4;
        float4 v0 = *(const float4*)&src[(size_t)(2*k2)*PP + px4];
        float4 v1 = *(const float4*)&src[(size_t)(2*k2+1)*PP + px4];
        __half2 tmp[4];
        tmp[0] = __floats2half2_rn(v0.x, v1.x);
        tmp[1] = __floats2half2_rn(v0.y, v1.y);
        tmp[2] = __floats2half2_rn(v0.z, v1.z);
        tmp[3] = __floats2half2_rn(v0.w, v1.w);
        *(uint4*)&xs2s[k2][px4] = *(uint4*)tmp;
    }
    __syncthreads();

    float acc[16][4];
    #pragma unroll
    for (int j = 0; j < 16; j++) { acc[j][0]=0.f; acc[j][1]=0.f; acc[j][2]=0.f; acc[j][3]=0.f; }

    #pragma unroll
    for (int kk = 0; kk < 4; kk++) {
        unsigned a[4];
        a[0] = h2u(ws2s[8*kk+lc]  [oc0+lr]);
        a[1] = h2u(ws2s[8*kk+lc]  [oc0+lr+8]);
        a[2] = h2u(ws2s[8*kk+lc+4][oc0+lr]);
        a[3] = h2u(ws2s[8*kk+lc+4][oc0+lr+8]);
        #pragma unroll
        for (int j = 0; j < 16; j++) {
            unsigned bfr[2];
            bfr[0] = h2u(xs2s[8*kk+lc]  [8*j+lr]);
            bfr[1] = h2u(xs2s[8*kk+lc+4][8*j+lr]);
            mma_f16(acc[j], a, bfr);
        }
    }
    __half2* dst2 = g_t02 + (size_t)b*32*PP + p0g;
    bool even = (lr & 1) == 0;
    int m = even ? (lr >> 1) : ((lr - 1) >> 1);
    int oc2 = 8*warp + (even ? m : 4 + m);
    #pragma unroll
    for (int j = 0; j < 16; j++) {
        unsigned u01 = packh2(acc[j][0], acc[j][1]);
        unsigned u23 = packh2(acc[j][2], acc[j][3]);
        uint2 v = pair_merge(u01, u23, even);
        *(uint2*)&dst2[(size_t)oc2*PP + 8*j + 2*lc] = v;
    }
}

// ================================================================================
// K2: ALL FOUR scans in one launch. grid (128, 4, 2):
//   y=0: down  y=1: up  (vertical, thread-per-column, prefetch-1)
//   y=2: right y=3: left (horizontal, warp transpose tiles)
//   z: column-half (vertical) or row-half (horizontal)
// Per-block resources identical to the R10 split kernels -> same occupancy,
// but 1024 blocks in flight instead of 2x512 serial.
// ================================================================================
__global__ __launch_bounds__(128)
void k_scan(const float* __restrict__ w_up, const float* __restrict__ b_up,
            const float* __restrict__ w_down, const float* __restrict__ b_down,
            const float* __restrict__ w_right, const float* __restrict__ b_right,
            const float* __restrict__ w_left, const float* __restrict__ b_left) {
    __shared__ __half2 s[4][32][33];
    int plane = blockIdx.x;               // b*32 + k2
    int k2    = plane & 31;
    int mode  = blockIdx.y;               // 0=down 1=up 2=right 3=left
    const __half2* src = g_t02 + (size_t)plane*PP;

    if (mode < 2) {
        int up = mode;                    // 0=down(fwd) 1=up(rev)
        int w  = blockIdx.z * 128 + threadIdx.x;
        __half2* dst = (up ? g_dir2[0] : g_dir2[2]) + (size_t)plane*PP;
        float wc0 = up ? w_up[2*k2]   : w_down[2*k2];
        float wc1 = up ? w_up[2*k2+1] : w_down[2*k2+1];
        float bv0 = up ? b_up[2*k2]   : b_down[2*k2];
        float bv1 = up ? b_up[2*k2+1] : b_down[2*k2+1];
        float h0 = 0.f, h1 = 0.f;
        if (!up) {
            float2 v = __half22float2(src[w]);
            #pragma unroll 4
            for (int y = 0; y < Hh; y++) {
                float2 vn = (y < Hh-1) ? __half22float2(src[(y+1)*Ww + w]) : make_float2(0.f,0.f);
                h0 = fmaxf(fmaf(wc0, h0, v.x + bv0), 0.f);
                h1 = fmaxf(fmaf(wc1, h1, v.y + bv1), 0.f);
                dst[y*Ww + w] = __floats2half2_rn(h0, h1);
                v = vn;
            }
        } else {
            float2 v = __half22float2(src[(Hh-1)*Ww + w]);
            #pragma unroll 4
            for (int y = Hh-1; y >= 0; y--) {
                float2 vn = (y > 0) ? __half22float2(src[(y-1)*Ww + w]) : make_float2(0.f,0.f);
                h0 = fmaxf(fmaf(wc0, h0, v.x + bv0), 0.f);
                h1 = fmaxf(fmaf(wc1, h1, v.y + bv1), 0.f);
                dst[y*Ww + w] = __floats2half2_rn(h0, h1);
                v = vn;
            }
        }
    } else {
        int lft = mode - 2;               // 0=right(fwd) 1=left(rev)
        int lane = threadIdx.x & 31, warp = threadIdx.x >> 5;
        __half2* dst = (lft ? g_dir2[3] : g_dir2[1]) + (size_t)plane*PP;
        float wc0 = lft ? w_left[2*k2]   : w_right[2*k2];
        float wc1 = lft ? w_left[2*k2+1] : w_right[2*k2+1];
        float bv0 = lft ? b_left[2*k2]   : b_right[2*k2];
        float bv1 = lft ? b_left[2*k2+1] : b_right[2*k2+1];
        int row0 = blockIdx.z * 128 + warp * 32;
        float h0 = 0.f, h1 = 0.f;
        for (int ch = 0; ch < 8; ch++) {
            int c0 = lft ? (224 - ch*32) : ch*32;
            #pragma unroll
            for (int r = 0; r < 32; r++)
                s[warp][r][lane] = src[(row0 + r)*Ww + c0 + lane];
            __syncwarp();
            if (!lft) {
                #pragma unroll
                for (int j = 0; j < 32; j++) {
                    float2 v = __half22float2(s[warp][lane][j]);
                    h0 = fmaxf(fmaf(wc0, h0, v.x + bv0), 0.f);
                    h1 = fmaxf(fmaf(wc1, h1, v.y + bv1), 0.f);
                    s[warp][lane][j] = __floats2half2_rn(h0, h1);
                }
            } else {
                #pragma unroll
                for (int j = 31; j >= 0; j--) {
                    float2 v = __half22float2(s[warp][lane][j]);
                    h0 = fmaxf(fmaf(wc0, h0, v.x + bv0), 0.f);
                    h1 = fmaxf(fmaf(wc1, h1, v.y + bv1), 0.f);
                    s[warp][lane][j] = __floats2half2_rn(h0, h1);
                }
            }
            __syncwarp();
            #pragma unroll
            for (int r = 0; r < 32; r++)
                dst[(row0 + r)*Ww + c0 + lane] = s[warp][r][lane];
            __syncwarp();
        }
    }
}

// ================================================================================
// K3: t2 = relu(wD2 @ cat). Staging from interleaved dir = pure uint4 copies.
// (R10 version — simple staging, no register pipeline.)
// ================================================================================
__global__ __launch_bounds__(128)
void k_convD2() {
    __shared__ __align__(16) __half2 ws2s[32][72];
    __shared__ __align__(16) __half2 xs2s[32][136];
    int tid  = threadIdx.x;
    int lane = tid & 31, warp = tid >> 5;
    int lr = lane >> 2, lc = lane & 3;
    int blk = blockIdx.x;                 // 2048
    int b   = blk >> 9;
    int p0g = (blk & 511) * 128;
    int oc0 = warp * 16;

    float acc[16][4];
    #pragma unroll
    for (int j = 0; j < 16; j++) { acc[j][0]=0.f; acc[j][1]=0.f; acc[j][2]=0.f; acc[j][3]=0.f; }

    for (int d = 0; d < 4; d++) {
        __syncthreads();
        const __half2* wsrc = g_wD22 + d*2048;
        for (int t = tid; t < 2048; t += 128) {
            int k2 = t >> 6, oc = t & 63;
            ws2s[k2][oc] = wsrc[t];
        }
        const __half2* srcd = (const __half2*)g_dir2[d] + (size_t)b*32*PP + p0g;
        for (int t = tid; t < 1024; t += 128) {
            int k2 = t >> 5, px4 = (t & 31) * 4;
            *(uint4*)&xs2s[k2][px4] = *(const uint4*)&srcd[(size_t)k2*PP + px4];
        }
        __syncthreads();
        #pragma unroll
        for (int kk = 0; kk < 4; kk++) {
            unsigned a[4];
            a[0] = h2u(ws2s[8*kk+lc]  [oc0+lr]);
            a[1] = h2u(ws2s[8*kk+lc]  [oc0+lr+8]);
            a[2] = h2u(ws2s[8*kk+lc+4][oc0+lr]);
            a[3] = h2u(ws2s[8*kk+lc+4][oc0+lr+8]);
            #pragma unroll
            for (int j = 0; j < 16; j++) {
                unsigned bfr[2];
                bfr[0] = h2u(xs2s[8*kk+lc]  [8*j+lr]);
                bfr[1] = h2u(xs2s[8*kk+lc+4][8*j+lr]);
                mma_f16(acc[j], a, bfr);
            }
        }
    }
    __half2* dst2 = g_t22 + (size_t)b*32*PP + p0g;
    bool even = (lr & 1) == 0;
    int m = even ? (lr >> 1) : ((lr - 1) >> 1);
    int oc2 = 8*warp + (even ? m : 4 + m);
    #pragma unroll
    for (int j = 0; j < 16; j++) {
        unsigned u01 = packh2(fmaxf(acc[j][0],0.f), fmaxf(acc[j][1],0.f));
        unsigned u23 = packh2(fmaxf(acc[j][2],0.f), fmaxf(acc[j][3],0.f));
        uint2 v = pair_merge(u01, u23, even);
        *(uint2*)&dst2[(size_t)oc2*PP + 8*j + 2*lc] = v;
    }
}

// ================================================================================
// K4/K5: conv3x3 SAME + relu via fp16 mma. Interleaved src: single half2 loads.
// ================================================================================
template<int IC, int LAYER>
__global__ __launch_bounds__(128)
void k_conv3(const float* __restrict__ bias) {
    __shared__ __align__(16) __half2 wsm2[9][8][40];
    __shared__ __align__(16) __half2 in_s2[8][10][36];

    const __half2* src2 = (LAYER == 0) ? g_t22 : g_a12;
    __half2*       dst2 = (LAYER == 0) ? g_a12 : g_a22;
    const __half2* wT   = (LAYER == 0) ? g_w3h0 : g_w3h1;
    constexpr int ICP = IC/2;

    int tid  = threadIdx.x;
    int lane = tid & 31, warp = tid >> 5;
    int lr = lane >> 2, lc = lane & 3;
    int blk = blockIdx.x;                              // 1024
    int b   = blk >> 8;
    int t   = blk & 255;
    int ty0 = (t >> 3) * 8;
    int tx0 = (t & 7) * 32;
    const __half2* sb = src2 + (size_t)b*ICP*PP;

    float acc[2][8][4];
    #pragma unroll
    for (int m = 0; m < 2; m++)
        #pragma unroll
        for (int j = 0; j < 8; j++)
            { acc[m][j][0]=0.f; acc[m][j][1]=0.f; acc[m][j][2]=0.f; acc[m][j][3]=0.f; }

    for (int ic20 = 0; ic20 < ICP; ic20 += 8) {
        __syncthreads();
        for (int tt = tid; tt < 8*9*32; tt += 128) {
            int oc = tt & 31;
            int q  = tt >> 5;
            int tap = q % 9, icl2 = q / 9;
            wsm2[tap][icl2][oc] = wT[((ic20 + icl2)*9 + tap)*32 + oc];
        }
        for (int tt = tid; tt < 8*10*34; tt += 128) {
            int col = tt % 34;
            int rr  = (tt / 34) % 10;
            int icl2 = tt / 340;
            int gy = ty0 + rr - 1, gx = tx0 + col - 1;
            __half2 v = __floats2half2_rn(0.f, 0.f);
            if (gy >= 0 && gy < Hh && gx >= 0 && gx < Ww)
                v = sb[(size_t)(ic20 + icl2)*PP + gy*Ww + gx];
            in_s2[icl2][rr][col] = v;
        }
        __syncthreads();

        #pragma unroll
        for (int tap = 0; tap < 9; tap++) {
            int dy = tap / 3, dx = tap % 3;
            unsigned aA[4], aB[4];
            aA[0] = h2u(wsm2[tap][lc]  [lr]);
            aA[1] = h2u(wsm2[tap][lc]  [lr+8]);
            aA[2] = h2u(wsm2[tap][lc+4][lr]);
            aA[3] = h2u(wsm2[tap][lc+4][lr+8]);
            aB[0] = h2u(wsm2[tap][lc]  [lr+16]);
            aB[1] = h2u(wsm2[tap][lc]  [lr+24]);
            aB[2] = h2u(wsm2[tap][lc+4][lr+16]);
            aB[3] = h2u(wsm2[tap][lc+4][lr+24]);
            #pragma unroll
            for (int j = 0; j < 8; j++) {
                int y = 2*warp + (j >> 2);
                int x = 8*(j & 3) + lr;
                unsigned bfr[2];
                bfr[0] = h2u(in_s2[lc]  [y+dy][x+dx]);
                bfr[1] = h2u(in_s2[lc+4][y+dy][x+dx]);
                mma_f16(acc[0][j], aA, bfr);
                mma_f16(acc[1][j], aB, bfr);
            }
        }
    }
    bool even = (lr & 1) == 0;
    int q = even ? (lr >> 1) : ((lr - 1) >> 1);
    #pragma unroll
    for (int m = 0; m < 2; m++) {
        int ocA = 16*m + lr, ocB = 16*m + lr + 8;
        float bA = bias[ocA], bB = bias[ocB];
        int oc2 = 8*m + (even ? q : 4 + q);
        #pragma unroll
        for (int j = 0; j < 8; j++) {
            int py = ty0 + 2*warp + (j >> 2);
            int px = tx0 + 8*(j & 3) + 2*lc;
            unsigned u01 = packh2(fmaxf(acc[m][j][0]+bA,0.f), fmaxf(acc[m][j][1]+bA,0.f));
            unsigned u23 = packh2(fmaxf(acc[m][j][2]+bB,0.f), fmaxf(acc[m][j][3]+bB,0.f));
            uint2 v = pair_merge(u01, u23, even);
            *(uint2*)&dst2[((size_t)b*16 + oc2)*PP + py*Ww + px] = v;
        }
    }
}

// ================================================================================
// K6: a = a3w @ a2 + a3b ; weight = sigmoid(a) ; out = relu(x * weight)
// ================================================================================
__global__ __launch_bounds__(256)
void k_final(const float* __restrict__ x, const float* __restrict__ a3w,
             const float* __restrict__ a3b, float* __restrict__ out) {
    int idx = blockIdx.x * 256 + threadIdx.x;       // 65536 groups of 4 px
    int b  = idx >> 14;
    int p4 = (idx & 16383) * 4;
    const __half2* a2 = g_a22 + (size_t)b*16*PP;
    float4 acc = make_float4(0.f, 0.f, 0.f, 0.f);
    #pragma unroll
    for (int ic2 = 0; ic2 < 16; ic2++) {
        float w0 = a3w[2*ic2], w1 = a3w[2*ic2+1];
        uint4 raw = *(const uint4*)&a2[(size_t)ic2*PP + p4];
        __half2* h = (__half2*)&raw;
        float2 f0 = __half22float2(h[0]);
        float2 f1 = __half22float2(h[1]);
        float2 f2 = __half22float2(h[2]);
        float2 f3 = __half22float2(h[3]);
        acc.x += w0*f0.x + w1*f0.y;
        acc.y += w0*f1.x + w1*f1.y;
        acc.z += w0*f2.x + w1*f2.y;
        acc.w += w0*f3.x + w1*f3.y;
    }
    float bb = a3b[0];
    float4 wt;
    wt.x = 1.f / (1.f + expf(-(acc.x + bb)));
    wt.y = 1.f / (1.f + expf(-(acc.y + bb)));
    wt.z = 1.f / (1.f + expf(-(acc.z + bb)));
    wt.w = 1.f / (1.f + expf(-(acc.w + bb)));
    #pragma unroll 4
    for (int c = 0; c < 64; c++) {
        float4 xv = *(const float4*)&x[((size_t)b*64 + c)*PP + p4];
        float4 o;
        o.x = fmaxf(xv.x * wt.x, 0.f);
        o.y = fmaxf(xv.y * wt.y, 0.f);
        o.z = fmaxf(xv.z * wt.z, 0.f);
        o.w = fmaxf(xv.w * wt.w, 0.f);
        *(float4*)&out[((size_t)b*64 + c)*PP + p4] = o;
    }
}

// ================================================================================
extern "C" void kernel_launch(void* const* d_in, const int* in_sizes, int n_in,
                              void* d_out, int out_size) {
    const float* x       = (const float*)d_in[0];
    const float* w_in    = (const float*)d_in[1];
    const float* w_up    = (const float*)d_in[2];
    const float* b_up    = (const float*)d_in[3];
    const float* w_right = (const float*)d_in[4];
    const float* b_right = (const float*)d_in[5];
    const float* w_down  = (const float*)d_in[6];
    const float* b_down  = (const float*)d_in[7];
    const float* w_left  = (const float*)d_in[8];
    const float* b_left  = (const float*)d_in[9];
    const float* wD2     = (const float*)d_in[10];
    const float* a1w     = (const float*)d_in[11];
    const float* a1b     = (const float*)d_in[12];
    const float* a2w     = (const float*)d_in[13];
    const float* a2b     = (const float*)d_in[14];
    const float* a3w     = (const float*)d_in[15];
    const float* a3b     = (const float*)d_in[16];
    float* out = (float*)d_out;

    k_prep<<<94, 256>>>(w_in, wD2, a1w, a2w);
    k_conv_in<<<2048, 128>>>(x);
    dim3 gscan(Bb*32, 4, 2);
    k_scan<<<gscan, 128>>>(w_up, b_up, w_down, b_down,
                           w_right, b_right, w_left, b_left);
    k_convD2<<<2048, 128>>>();
    k_conv3<64, 0><<<1024, 128>>>(a1b);
    k_conv3<32, 1><<<1024, 128>>>(a2b);
    k_final<<<256, 256>>>(x, a3w, a3b, out);
}